// round 1
// baseline (speedup 1.0000x reference)
#include <cuda_runtime.h>
#include <cstdint>

// ---------------- problem constants ----------------
#define HH 128
#define WW 256
#define HW (HH*WW)          // 32768 pixels
#define CC 256
#define KTAP 9
#define NSAMP (HW*KTAP)     // 294912
#define NHEAD 8
#define DH 32

// ---------------- static device scratch ----------------
__device__ float g_XT[(size_t)HW*CC];       // x transposed [hw][c]   33.5MB
__device__ int   g_idx[NSAMP];              // gather indices         1.2MB
__device__ float g_wqT[CC*CC];
__device__ float g_wkT[CC*CC];
__device__ float g_wvT[CC*CC];
__device__ float g_Q[(size_t)HW*CC];        // [p][o] 33.5MB
__device__ float g_K[(size_t)NSAMP*CC];     // [s][o] 302MB
__device__ float g_V[(size_t)NSAMP*CC];     // [s][o] 302MB
__device__ float g_OUT[(size_t)CC*HW];      // [c][p] 33.5MB (channel-major)

// ---------------- index computation ----------------
// idx[s]: s = pixel*9 + tap, pixel = h*W + w, tap = kh*3 + kw
__global__ void idx_kernel(const float* __restrict__ grid, int* __restrict__ idx)
{
    int s = blockIdx.x * 256 + threadIdx.x;
    if (s >= NSAMP) return;
    int p  = s / 9;
    int t  = s - p * 9;
    int h  = p >> 8;          // p / 256
    int w  = p & 255;
    int kh = t / 3;
    int kw = t - kh * 3;
    int r  = h * 3 + kh;      // row in grid (384)
    int cc = w * 3 + kw;      // col in grid (768)
    const float* g = grid + ((size_t)r * 768 + cc) * 2;
    float gx = g[0];
    float gy = g[1];
    // match jnp: round-half-even then clip
    float fx = rintf(((gx + 1.0f) * 0.5f) * 255.0f);
    float fy = rintf(((gy + 1.0f) * 0.5f) * 127.0f);
    int ix = (int)fminf(fmaxf(fx, 0.0f), 255.0f);
    int iy = (int)fminf(fmaxf(fy, 0.0f), 127.0f);
    idx[s] = iy * WW + ix;
}

// ---------------- generic tiled transpose: in[rows][cols] -> out[cols][rows] ----------------
__global__ void transpose_k(const float* __restrict__ in, float* __restrict__ out,
                            int rows, int cols)
{
    __shared__ float tile[32][33];
    int c0 = blockIdx.x * 32;
    int r0 = blockIdx.y * 32;
    int tx = threadIdx.x;
    int ty = threadIdx.y;
#pragma unroll
    for (int i = 0; i < 32; i += 8)
        tile[ty + i][tx] = in[(size_t)(r0 + ty + i) * cols + c0 + tx];
    __syncthreads();
#pragma unroll
    for (int i = 0; i < 32; i += 8)
        out[(size_t)(c0 + ty + i) * rows + r0 + tx] = tile[tx][ty + i];
}

// ---------------- 128x128x8 double-buffered SGEMM ----------------
// C[M][N] = A[M][K=256] * B[256][N] + bias
// GATHER: A row m is A[gidx[m]] (gathered rows of XT)
// ROWBIAS: bias indexed by m (else by n)
template<bool GATHER, bool ROWBIAS>
__global__ __launch_bounds__(256, 2)
void gemm_tile(const float* __restrict__ A, const float* __restrict__ B,
               const float* __restrict__ bias, float* __restrict__ C,
               const int* __restrict__ gidx, int M, int N)
{
    const int Kd = 256;
    __shared__ __align__(16) float As[2][8][128];
    __shared__ __align__(16) float Bs[2][8][128];
    __shared__ int ridx[128];

    int tid = threadIdx.x;
    int m0 = blockIdx.y * 128;
    int n0 = blockIdx.x * 128;

    int am = tid >> 1;              // 0..127
    int ak = (tid & 1) << 2;        // 0 or 4
    int bk = tid >> 5;              // 0..7
    int bn = (tid & 31) << 2;       // 0..124

    if (GATHER) {
        if (tid < 128) ridx[tid] = gidx[m0 + tid];
        __syncthreads();
    }
    const float* Aptr;
    {
        int grow = GATHER ? ridx[am] : (m0 + am);
        Aptr = A + (size_t)grow * Kd + ak;
    }
    const float* Bptr = B + (size_t)bk * N + n0 + bn;

    float acc[8][8];
#pragma unroll
    for (int i = 0; i < 8; i++)
#pragma unroll
        for (int j = 0; j < 8; j++) acc[i][j] = 0.0f;

    float4 a4 = *(const float4*)Aptr;
    float4 b4 = *(const float4*)Bptr;
    As[0][ak + 0][am] = a4.x;
    As[0][ak + 1][am] = a4.y;
    As[0][ak + 2][am] = a4.z;
    As[0][ak + 3][am] = a4.w;
    *(float4*)&Bs[0][bk][bn] = b4;
    __syncthreads();

    int tx = tid & 15;   // n-frag
    int ty = tid >> 4;   // m-frag

    const int NK = Kd / 8;  // 32
    int buf = 0;
#pragma unroll 1
    for (int ks = 0; ks < NK; ks++) {
        if (ks + 1 < NK) {
            a4 = *(const float4*)(Aptr + (ks + 1) * 8);
            b4 = *(const float4*)(Bptr + (size_t)(ks + 1) * 8 * N);
        }
#pragma unroll
        for (int kk = 0; kk < 8; kk++) {
            float af[8], bf[8];
            float4 t0 = *(const float4*)&As[buf][kk][ty * 8];
            float4 t1 = *(const float4*)&As[buf][kk][ty * 8 + 4];
            float4 t2 = *(const float4*)&Bs[buf][kk][tx * 8];
            float4 t3 = *(const float4*)&Bs[buf][kk][tx * 8 + 4];
            af[0]=t0.x; af[1]=t0.y; af[2]=t0.z; af[3]=t0.w;
            af[4]=t1.x; af[5]=t1.y; af[6]=t1.z; af[7]=t1.w;
            bf[0]=t2.x; bf[1]=t2.y; bf[2]=t2.z; bf[3]=t2.w;
            bf[4]=t3.x; bf[5]=t3.y; bf[6]=t3.z; bf[7]=t3.w;
#pragma unroll
            for (int i = 0; i < 8; i++)
#pragma unroll
                for (int j = 0; j < 8; j++)
                    acc[i][j] += af[i] * bf[j];
        }
        if (ks + 1 < NK) {
            buf ^= 1;
            As[buf][ak + 0][am] = a4.x;
            As[buf][ak + 1][am] = a4.y;
            As[buf][ak + 2][am] = a4.z;
            As[buf][ak + 3][am] = a4.w;
            *(float4*)&Bs[buf][bk][bn] = b4;
            __syncthreads();
        }
    }

    // epilogue + bias
    float bvv[8];
    if (ROWBIAS) {
#pragma unroll
        for (int i = 0; i < 8; i++) bvv[i] = bias[m0 + ty * 8 + i];
    } else {
#pragma unroll
        for (int j = 0; j < 8; j++) bvv[j] = bias[n0 + tx * 8 + j];
    }
#pragma unroll
    for (int i = 0; i < 8; i++) {
        size_t rowoff = (size_t)(m0 + ty * 8 + i) * N + n0 + tx * 8;
        float4 o0, o1;
        if (ROWBIAS) {
            o0.x = acc[i][0] + bvv[i]; o0.y = acc[i][1] + bvv[i];
            o0.z = acc[i][2] + bvv[i]; o0.w = acc[i][3] + bvv[i];
            o1.x = acc[i][4] + bvv[i]; o1.y = acc[i][5] + bvv[i];
            o1.z = acc[i][6] + bvv[i]; o1.w = acc[i][7] + bvv[i];
        } else {
            o0.x = acc[i][0] + bvv[0]; o0.y = acc[i][1] + bvv[1];
            o0.z = acc[i][2] + bvv[2]; o0.w = acc[i][3] + bvv[3];
            o1.x = acc[i][4] + bvv[4]; o1.y = acc[i][5] + bvv[5];
            o1.z = acc[i][6] + bvv[6]; o1.w = acc[i][7] + bvv[7];
        }
        *(float4*)(C + rowoff)     = o0;
        *(float4*)(C + rowoff + 4) = o1;
    }
}

// ---------------- attention: per (pixel, head) 9-tap softmax ----------------
// Q [p][256], K/V [s=p*9+t][256]  ->  OUT channel-major [c][p]
__global__ __launch_bounds__(256)
void attn_kernel(const float* __restrict__ Q, const float* __restrict__ Km,
                 const float* __restrict__ Vm, float* __restrict__ OUTcm)
{
    __shared__ float outs[256][33];   // [channel][pixel-in-tile], padded
    int p0   = blockIdx.x << 5;       // 32 pixels per block
    int warp = threadIdx.x >> 5;
    int lane = threadIdx.x & 31;
    const float scale = 0.17677669529663687f;  // 1/sqrt(32)

#pragma unroll 1
    for (int task = warp; task < 256; task += 8) {
        int p  = task >> 3;
        int h  = task & 7;
        int pg = p0 + p;
        float qd = Q[(size_t)pg * 256 + h * 32 + lane];
        const float* kb = Km + (size_t)pg * 9 * 256 + h * 32 + lane;
        const float* vb = Vm + (size_t)pg * 9 * 256 + h * 32 + lane;
        float lg[9];
#pragma unroll
        for (int t = 0; t < 9; t++) {
            float prod = qd * kb[t * 256];
#pragma unroll
            for (int off = 16; off > 0; off >>= 1)
                prod += __shfl_xor_sync(0xffffffffu, prod, off);
            lg[t] = prod * scale;
        }
        float mx = lg[0];
#pragma unroll
        for (int t = 1; t < 9; t++) mx = fmaxf(mx, lg[t]);
        float den = 0.0f, e[9];
#pragma unroll
        for (int t = 0; t < 9; t++) { e[t] = __expf(lg[t] - mx); den += e[t]; }
        float inv = 1.0f / den;
        float o = 0.0f;
#pragma unroll
        for (int t = 0; t < 9; t++) o += e[t] * vb[t * 256];
        outs[h * 32 + lane][p] = o * inv;
    }
    __syncthreads();
    // coalesced channel-major writes: warp w writes channels w, w+8, ...
#pragma unroll 1
    for (int r = 0; r < 32; r++) {
        int c = r * 8 + warp;
        OUTcm[(size_t)c * HW + p0 + lane] = outs[c][lane];
    }
}

// ---------------- launch ----------------
extern "C" void kernel_launch(void* const* d_in, const int* in_sizes, int n_in,
                              void* d_out, int out_size)
{
    const float* x   = (const float*)d_in[0];
    const float* grd = (const float*)d_in[1];
    const float* wq  = (const float*)d_in[2];
    const float* bq  = (const float*)d_in[3];
    const float* wk  = (const float*)d_in[4];
    const float* bk  = (const float*)d_in[5];
    const float* wv  = (const float*)d_in[6];
    const float* bv  = (const float*)d_in[7];
    const float* wo  = (const float*)d_in[8];
    const float* bo  = (const float*)d_in[9];
    float* y = (float*)d_out;

    float *XT, *wqT, *wkT, *wvT, *Qm, *Km, *Vm, *OUT;
    int* idx;
    cudaGetSymbolAddress((void**)&XT,  g_XT);
    cudaGetSymbolAddress((void**)&idx, g_idx);
    cudaGetSymbolAddress((void**)&wqT, g_wqT);
    cudaGetSymbolAddress((void**)&wkT, g_wkT);
    cudaGetSymbolAddress((void**)&wvT, g_wvT);
    cudaGetSymbolAddress((void**)&Qm,  g_Q);
    cudaGetSymbolAddress((void**)&Km,  g_K);
    cudaGetSymbolAddress((void**)&Vm,  g_V);
    cudaGetSymbolAddress((void**)&OUT, g_OUT);

    // 1) gather indices
    idx_kernel<<<NSAMP / 256, 256>>>(grd, idx);

    // 2) transposes: x -> XT[hw][c]; weights -> [c][o]
    dim3 tb(32, 8);
    transpose_k<<<dim3(HW / 32, CC / 32), tb>>>(x,  XT,  CC, HW);
    transpose_k<<<dim3(CC / 32, CC / 32), tb>>>(wq, wqT, CC, CC);
    transpose_k<<<dim3(CC / 32, CC / 32), tb>>>(wk, wkT, CC, CC);
    transpose_k<<<dim3(CC / 32, CC / 32), tb>>>(wv, wvT, CC, CC);

    // 3) projections
    // Q[p][o] = XT[p][c] * wqT[c][o] + bq[o]
    gemm_tile<false, false><<<dim3(CC / 128, HW / 128), 256>>>(XT, wqT, bq, Qm, nullptr, HW, CC);
    // K[s][o] = XT[idx[s]][c] * wkT[c][o] + bk[o]
    gemm_tile<true,  false><<<dim3(CC / 128, NSAMP / 128), 256>>>(XT, wkT, bk, Km, idx, NSAMP, CC);
    // V[s][o]
    gemm_tile<true,  false><<<dim3(CC / 128, NSAMP / 128), 256>>>(XT, wvT, bv, Vm, idx, NSAMP, CC);

    // 4) attention -> OUT[c][p] (channel-major)
    attn_kernel<<<HW / 32, 256>>>(Qm, Km, Vm, OUT);

    // 5) y[o][p] = wo[o][c] * OUT[c][p] + bo[o]   (directly in output layout)
    gemm_tile<false, true><<<dim3(HW / 128, CC / 128), 256>>>(wo, OUT, bo, y, nullptr, CC, HW);
}

// round 3
// speedup vs baseline: 2.0033x; 2.0033x over previous
#include <cuda_runtime.h>
#include <cuda_bf16.h>
#include <cstdint>

// ---------------- problem constants ----------------
#define HH 128
#define WW 256
#define HW (HH*WW)          // 32768
#define CC 256
#define NSAMP (HW*9)        // 294912

// ---------------- static device scratch ----------------
__device__ __nv_bfloat16 g_XTh[(size_t)HW*CC];
__device__ __nv_bfloat16 g_XTl[(size_t)HW*CC];
__device__ int           g_idx[NSAMP];
__device__ __nv_bfloat16 g_Wh[4*CC*CC];   // q,k,v,o
__device__ __nv_bfloat16 g_Wl[4*CC*CC];
__device__ float         g_Q[(size_t)HW*CC];
__device__ float         g_K[(size_t)NSAMP*CC];
__device__ float         g_V[(size_t)NSAMP*CC];
__device__ __nv_bfloat16 g_OUTh[(size_t)HW*CC];
__device__ __nv_bfloat16 g_OUTl[(size_t)HW*CC];

// ---------------- helpers ----------------
__device__ __forceinline__ uint32_t smem_u32(const void* p) {
    uint32_t a;
    asm("{ .reg .u64 t; cvta.to.shared.u64 t, %1; cvt.u32.u64 %0, t; }" : "=r"(a) : "l"(p));
    return a;
}
#define LDSM_X4(r, a) \
    asm volatile("ldmatrix.sync.aligned.m8n8.x4.shared.b16 {%0,%1,%2,%3}, [%4];" \
        : "=r"((r)[0]), "=r"((r)[1]), "=r"((r)[2]), "=r"((r)[3]) : "r"(a))

#define MMA16816(d, a, b) \
    asm volatile("mma.sync.aligned.m16n8k16.row.col.f32.bf16.bf16.f32 " \
        "{%0,%1,%2,%3}, {%4,%5,%6,%7}, {%8,%9}, {%0,%1,%2,%3};" \
        : "+f"((d)[0]), "+f"((d)[1]), "+f"((d)[2]), "+f"((d)[3]) \
        : "r"((a)[0]), "r"((a)[1]), "r"((a)[2]), "r"((a)[3]), "r"((b)[0]), "r"((b)[1]))

// SMEM layout (bytes): A tiles [2 buf][hi/lo][128 rows][80B], B same, ridx
#define LDS_ROW   80
#define TILE_HB   (128*LDS_ROW)      // 10240 per (buf,hi/lo) plane
#define BUF_SZ    (2*TILE_HB)        // 20480 per buffer (hi+lo)
#define AS_OFF    0
#define BS_OFF    (2*BUF_SZ)         // 40960
#define RIDX_OFF  (4*BUF_SZ)         // 81920
#define SMEM_SZ   (RIDX_OFF + 512)   // 82432

// ---------------- index computation ----------------
__global__ void idx_kernel(const float* __restrict__ grid, int* __restrict__ idx)
{
    int s = blockIdx.x * 256 + threadIdx.x;
    if (s >= NSAMP) return;
    int p  = s / 9;
    int t  = s - p * 9;
    int h  = p >> 8;
    int w  = p & 255;
    int kh = t / 3;
    int kw = t - kh * 3;
    const float* g = grid + ((size_t)(h * 3 + kh) * 768 + (w * 3 + kw)) * 2;
    float fx = rintf(((g[0] + 1.0f) * 0.5f) * 255.0f);
    float fy = rintf(((g[1] + 1.0f) * 0.5f) * 127.0f);
    int ix = (int)fminf(fmaxf(fx, 0.0f), 255.0f);
    int iy = (int)fminf(fmaxf(fy, 0.0f), 127.0f);
    idx[s] = iy * WW + ix;
}

// ---------------- transpose x[C][HW] -> XTh/XTl [HW][C] ----------------
__global__ void transpose_conv(const float* __restrict__ in,
                               __nv_bfloat16* __restrict__ oh, __nv_bfloat16* __restrict__ ol)
{
    __shared__ float tile[32][33];
    int c0 = blockIdx.x * 32;   // hw
    int r0 = blockIdx.y * 32;   // channel
    int tx = threadIdx.x, ty = threadIdx.y;
#pragma unroll
    for (int i = 0; i < 32; i += 8)
        tile[ty + i][tx] = in[(size_t)(r0 + ty + i) * HW + c0 + tx];
    __syncthreads();
#pragma unroll
    for (int i = 0; i < 32; i += 8) {
        float v = tile[tx][ty + i];
        __nv_bfloat16 h = __float2bfloat16(v);
        size_t o = (size_t)(c0 + ty + i) * CC + r0 + tx;
        oh[o] = h;
        ol[o] = __float2bfloat16(v - __bfloat162float(h));
    }
}

__global__ void conv_hilo(const float* __restrict__ src,
                          __nv_bfloat16* __restrict__ h, __nv_bfloat16* __restrict__ l)
{
    int i = blockIdx.x * 256 + threadIdx.x;
    float v = src[i];
    __nv_bfloat16 hi = __float2bfloat16(v);
    h[i] = hi;
    l[i] = __float2bfloat16(v - __bfloat162float(hi));
}

// ---------------- HMMA bf16-split GEMM ----------------
// C[M][N] = A[M][256] * B[N][256]^T + bias.  A,B bf16 hi/lo, K-contiguous rows.
// GATHER: A row m comes from gidx[m]. ROWBIAS: bias per m, else per n.
template<bool GATHER, bool ROWBIAS>
__global__ __launch_bounds__(256, 1)
void hmma_gemm(const __nv_bfloat16* __restrict__ Ah, const __nv_bfloat16* __restrict__ Al,
               const __nv_bfloat16* __restrict__ Bh, const __nv_bfloat16* __restrict__ Bl,
               const int* __restrict__ gidx, const float* __restrict__ bias,
               float* __restrict__ C, int ldc)
{
    extern __shared__ __align__(16) char sm[];
    uint32_t smb = smem_u32(sm);
    int tid = threadIdx.x;
    int m0 = blockIdx.y * 128, n0 = blockIdx.x * 128;

    if (GATHER) {
        if (tid < 128) ((int*)(sm + RIDX_OFF))[tid] = gidx[m0 + tid];
        __syncthreads();
    }

    // global load assignment: 2 threads per row, 2 chunks (uint4 = 8 halves) each
    int grow_l = tid >> 1;            // 0..127
    int gcp    = (tid & 1) * 2;       // 0 or 2
    int ga = GATHER ? ((const int*)(sm + RIDX_OFF))[grow_l] : (m0 + grow_l);
    const uint4* gAh = (const uint4*)(Ah + (size_t)ga * 256) + gcp;
    const uint4* gAl = (const uint4*)(Al + (size_t)ga * 256) + gcp;
    const uint4* gBh = (const uint4*)(Bh + (size_t)(n0 + grow_l) * 256) + gcp;
    const uint4* gBl = (const uint4*)(Bl + (size_t)(n0 + grow_l) * 256) + gcp;

    uint4 rA[4], rB[4];   // staging: [hi0, hi1, lo0, lo1]
    int store_off = grow_l * LDS_ROW + gcp * 16;

    // fragment smem addresses (within a buffer, hi plane)
    int wid = tid >> 5, lane = tid & 31;
    int wm = wid >> 2, wn = wid & 3;
    uint32_t aAddr[4], bAddr[2];
#pragma unroll
    for (int mt = 0; mt < 4; mt++)
        aAddr[mt] = smb + AS_OFF + (wm * 64 + mt * 16 + (lane & 15)) * LDS_ROW
                  + ((lane >> 4) * 16);
#pragma unroll
    for (int bt = 0; bt < 2; bt++)
        bAddr[bt] = smb + BS_OFF + (wn * 32 + bt * 16 + ((lane >> 4) & 1) * 8 + (lane & 7)) * LDS_ROW
                  + (((lane >> 3) & 1) * 16);

    float acc[4][4][4];
#pragma unroll
    for (int i = 0; i < 4; i++)
#pragma unroll
        for (int j = 0; j < 4; j++)
#pragma unroll
            for (int k = 0; k < 4; k++) acc[i][j][k] = 0.0f;

    // ---- prologue: load ks=0 ----
    rA[0] = gAh[0]; rA[1] = gAh[1]; rA[2] = gAl[0]; rA[3] = gAl[1];
    rB[0] = gBh[0]; rB[1] = gBh[1]; rB[2] = gBl[0]; rB[3] = gBl[1];
    {
        char* a = sm + AS_OFF + store_off;
        *(uint4*)a = rA[0]; *(uint4*)(a + 16) = rA[1];
        *(uint4*)(a + TILE_HB) = rA[2]; *(uint4*)(a + TILE_HB + 16) = rA[3];
        char* b = sm + BS_OFF + store_off;
        *(uint4*)b = rB[0]; *(uint4*)(b + 16) = rB[1];
        *(uint4*)(b + TILE_HB) = rB[2]; *(uint4*)(b + TILE_HB + 16) = rB[3];
    }
    __syncthreads();

#pragma unroll 1
    for (int ks = 0; ks < 8; ks++) {
        if (ks < 7) {
            int c = (ks + 1) * 4;
            rA[0] = gAh[c]; rA[1] = gAh[c + 1]; rA[2] = gAl[c]; rA[3] = gAl[c + 1];
            rB[0] = gBh[c]; rB[1] = gBh[c + 1]; rB[2] = gBl[c]; rB[3] = gBl[c + 1];
        }
        uint32_t boff = (ks & 1) * BUF_SZ;
#pragma unroll
        for (int kk = 0; kk < 2; kk++) {
            uint32_t ko = boff + kk * 32;
            uint32_t a_h[4][4], a_l[4][4];
#pragma unroll
            for (int mt = 0; mt < 4; mt++) {
                LDSM_X4(a_h[mt], aAddr[mt] + ko);
                LDSM_X4(a_l[mt], aAddr[mt] + ko + TILE_HB);
            }
            uint32_t b_h[2][4], b_l[2][4];
#pragma unroll
            for (int bt = 0; bt < 2; bt++) {
                LDSM_X4(b_h[bt], bAddr[bt] + ko);
                LDSM_X4(b_l[bt], bAddr[bt] + ko + TILE_HB);
            }
#pragma unroll
            for (int mt = 0; mt < 4; mt++)
#pragma unroll
                for (int nt = 0; nt < 4; nt++) {
                    uint32_t* bh = &b_h[nt >> 1][(nt & 1) * 2];
                    uint32_t* bl = &b_l[nt >> 1][(nt & 1) * 2];
                    MMA16816(acc[mt][nt], a_h[mt], bh);
                    MMA16816(acc[mt][nt], a_h[mt], bl);
                    MMA16816(acc[mt][nt], a_l[mt], bh);
                }
        }
        if (ks < 7) {
            uint32_t nb = ((ks + 1) & 1) * BUF_SZ;
            char* a = sm + AS_OFF + nb + store_off;
            *(uint4*)a = rA[0]; *(uint4*)(a + 16) = rA[1];
            *(uint4*)(a + TILE_HB) = rA[2]; *(uint4*)(a + TILE_HB + 16) = rA[3];
            char* b = sm + BS_OFF + nb + store_off;
            *(uint4*)b = rB[0]; *(uint4*)(b + 16) = rB[1];
            *(uint4*)(b + TILE_HB) = rB[2]; *(uint4*)(b + TILE_HB + 16) = rB[3];
            __syncthreads();
        }
    }

    // ---- epilogue ----
#pragma unroll
    for (int mt = 0; mt < 4; mt++) {
        int r0 = m0 + wm * 64 + mt * 16 + (lane >> 2);
        float rb0 = 0.f, rb1 = 0.f;
        if (ROWBIAS) { rb0 = bias[r0]; rb1 = bias[r0 + 8]; }
#pragma unroll
        for (int nt = 0; nt < 4; nt++) {
            int col = n0 + wn * 32 + nt * 8 + (lane & 3) * 2;
            float cb0 = 0.f, cb1 = 0.f;
            if (!ROWBIAS) { cb0 = bias[col]; cb1 = bias[col + 1]; }
            float* p = C + (size_t)r0 * ldc + col;
            float2 v;
            v.x = acc[mt][nt][0] + (ROWBIAS ? rb0 : cb0);
            v.y = acc[mt][nt][1] + (ROWBIAS ? rb0 : cb1);
            *(float2*)p = v;
            v.x = acc[mt][nt][2] + (ROWBIAS ? rb1 : cb0);
            v.y = acc[mt][nt][3] + (ROWBIAS ? rb1 : cb1);
            *(float2*)(p + (size_t)8 * ldc) = v;
        }
    }
}

// ---------------- attention: per (pixel, head) 9-tap softmax ----------------
__global__ __launch_bounds__(256)
void attn_kernel(const float* __restrict__ Q, const float* __restrict__ Km,
                 const float* __restrict__ Vm,
                 __nv_bfloat16* __restrict__ OUTh, __nv_bfloat16* __restrict__ OUTl)
{
    int p0   = blockIdx.x << 5;
    int warp = threadIdx.x >> 5;
    int lane = threadIdx.x & 31;
    const float scale = 0.17677669529663687f;  // 1/sqrt(32)

#pragma unroll 1
    for (int task = warp; task < 256; task += 8) {
        int p  = task >> 3;
        int h  = task & 7;
        int pg = p0 + p;
        float qd = Q[(size_t)pg * 256 + h * 32 + lane];
        const float* kb = Km + (size_t)pg * 9 * 256 + h * 32 + lane;
        const float* vb = Vm + (size_t)pg * 9 * 256 + h * 32 + lane;
        float lg[9];
#pragma unroll
        for (int t = 0; t < 9; t++) {
            float prod = qd * kb[t * 256];
#pragma unroll
            for (int off = 16; off > 0; off >>= 1)
                prod += __shfl_xor_sync(0xffffffffu, prod, off);
            lg[t] = prod * scale;
        }
        float mx = lg[0];
#pragma unroll
        for (int t = 1; t < 9; t++) mx = fmaxf(mx, lg[t]);
        float den = 0.0f, e[9];
#pragma unroll
        for (int t = 0; t < 9; t++) { e[t] = __expf(lg[t] - mx); den += e[t]; }
        float inv = 1.0f / den;
        float o = 0.0f;
#pragma unroll
        for (int t = 0; t < 9; t++) o += e[t] * vb[t * 256];
        float val = o * inv;
        __nv_bfloat16 hi = __float2bfloat16(val);
        size_t oi = (size_t)pg * 256 + h * 32 + lane;
        OUTh[oi] = hi;
        OUTl[oi] = __float2bfloat16(val - __bfloat162float(hi));
    }
}

// ---------------- launch ----------------
extern "C" void kernel_launch(void* const* d_in, const int* in_sizes, int n_in,
                              void* d_out, int out_size)
{
    const float* x   = (const float*)d_in[0];
    const float* grd = (const float*)d_in[1];
    const float* wq  = (const float*)d_in[2];
    const float* bq  = (const float*)d_in[3];
    const float* wk  = (const float*)d_in[4];
    const float* bk  = (const float*)d_in[5];
    const float* wv  = (const float*)d_in[6];
    const float* bv  = (const float*)d_in[7];
    const float* wo  = (const float*)d_in[8];
    const float* bo  = (const float*)d_in[9];
    float* y = (float*)d_out;

    __nv_bfloat16 *XTh, *XTl, *Wh, *Wl, *OUTh, *OUTl;
    float *Qm, *Km, *Vm;
    int* idx;
    cudaGetSymbolAddress((void**)&XTh,  g_XTh);
    cudaGetSymbolAddress((void**)&XTl,  g_XTl);
    cudaGetSymbolAddress((void**)&idx,  g_idx);
    cudaGetSymbolAddress((void**)&Wh,   g_Wh);
    cudaGetSymbolAddress((void**)&Wl,   g_Wl);
    cudaGetSymbolAddress((void**)&Qm,   g_Q);
    cudaGetSymbolAddress((void**)&Km,   g_K);
    cudaGetSymbolAddress((void**)&Vm,   g_V);
    cudaGetSymbolAddress((void**)&OUTh, g_OUTh);
    cudaGetSymbolAddress((void**)&OUTl, g_OUTl);

    cudaFuncSetAttribute(hmma_gemm<false, false>, cudaFuncAttributeMaxDynamicSharedMemorySize, SMEM_SZ);
    cudaFuncSetAttribute(hmma_gemm<true,  false>, cudaFuncAttributeMaxDynamicSharedMemorySize, SMEM_SZ);
    cudaFuncSetAttribute(hmma_gemm<false, true >, cudaFuncAttributeMaxDynamicSharedMemorySize, SMEM_SZ);

    // 1) gather indices
    idx_kernel<<<NSAMP / 256, 256>>>(grd, idx);

    // 2) x -> XT bf16 hi/lo ; weights -> bf16 hi/lo
    transpose_conv<<<dim3(HW / 32, CC / 32), dim3(32, 8)>>>(x, XTh, XTl);
    conv_hilo<<<CC * CC / 256, 256>>>(wq, Wh + 0 * CC * CC, Wl + 0 * CC * CC);
    conv_hilo<<<CC * CC / 256, 256>>>(wk, Wh + 1 * CC * CC, Wl + 1 * CC * CC);
    conv_hilo<<<CC * CC / 256, 256>>>(wv, Wh + 2 * CC * CC, Wl + 2 * CC * CC);
    conv_hilo<<<CC * CC / 256, 256>>>(wo, Wh + 3 * CC * CC, Wl + 3 * CC * CC);

    // 3) projections: C[m=pixel/sample][n=channel]
    hmma_gemm<false, false><<<dim3(CC / 128, HW / 128), 256, SMEM_SZ>>>(
        XTh, XTl, Wh + 0 * CC * CC, Wl + 0 * CC * CC, nullptr, bq, Qm, CC);
    hmma_gemm<true, false><<<dim3(CC / 128, NSAMP / 128), 256, SMEM_SZ>>>(
        XTh, XTl, Wh + 1 * CC * CC, Wl + 1 * CC * CC, idx, bk, Km, CC);
    hmma_gemm<true, false><<<dim3(CC / 128, NSAMP / 128), 256, SMEM_SZ>>>(
        XTh, XTl, Wh + 2 * CC * CC, Wl + 2 * CC * CC, idx, bv, Vm, CC);

    // 4) attention -> OUT bf16 hi/lo, pixel-major [p][c]
    attn_kernel<<<HW / 32, 256>>>(Qm, Km, Vm, OUTh, OUTl);

    // 5) y[o][p] = wo[o][c] * OUT[p][c]^T + bo[o]   (A = wo rows, B = OUT rows)
    hmma_gemm<false, true><<<dim3(HW / 128, CC / 128), 256, SMEM_SZ>>>(
        Wh + 3 * CC * CC, Wl + 3 * CC * CC, OUTh, OUTl, nullptr, bo, y, HW);
}

// round 4
// speedup vs baseline: 6.2957x; 3.1426x over previous
#include <cuda_runtime.h>
#include <cuda_bf16.h>
#include <cstdint>

// ---------------- problem constants ----------------
#define HH 128
#define WW 256
#define HW (HH*WW)          // 32768
#define CC 256
#define NSAMP (HW*9)        // 294912

// ---------------- static device scratch ----------------
__device__ __nv_bfloat16 g_XTh[(size_t)HW*CC];
__device__ __nv_bfloat16 g_XTl[(size_t)HW*CC];
__device__ int           g_idx[NSAMP];
__device__ __nv_bfloat16 g_Wh[4*CC*CC];   // q,k,v,o (q|k|v rows contiguous = fused B)
__device__ __nv_bfloat16 g_Wl[4*CC*CC];
__device__ float         g_bqkv[3*CC];
__device__ float         g_QKV[(size_t)HW*3*CC];   // [pixel][768] = Q|K|V   96MB
__device__ __nv_bfloat16 g_OUTh[(size_t)HW*CC];
__device__ __nv_bfloat16 g_OUTl[(size_t)HW*CC];

// ---------------- helpers ----------------
__device__ __forceinline__ uint32_t smem_u32(const void* p) {
    uint32_t a;
    asm("{ .reg .u64 t; cvta.to.shared.u64 t, %1; cvt.u32.u64 %0, t; }" : "=r"(a) : "l"(p));
    return a;
}
#define LDSM_X4(r, a) \
    asm volatile("ldmatrix.sync.aligned.m8n8.x4.shared.b16 {%0,%1,%2,%3}, [%4];" \
        : "=r"((r)[0]), "=r"((r)[1]), "=r"((r)[2]), "=r"((r)[3]) : "r"(a))

#define MMA16816(d, a, b) \
    asm volatile("mma.sync.aligned.m16n8k16.row.col.f32.bf16.bf16.f32 " \
        "{%0,%1,%2,%3}, {%4,%5,%6,%7}, {%8,%9}, {%0,%1,%2,%3};" \
        : "+f"((d)[0]), "+f"((d)[1]), "+f"((d)[2]), "+f"((d)[3]) \
        : "r"((a)[0]), "r"((a)[1]), "r"((a)[2]), "r"((a)[3]), "r"((b)[0]), "r"((b)[1]))

// SMEM layout (bytes): A tiles [2 buf][hi/lo][128 rows][80B], B same
#define LDS_ROW   80
#define TILE_HB   (128*LDS_ROW)      // 10240 per (buf,hi/lo) plane
#define BUF_SZ    (2*TILE_HB)        // 20480 per buffer (hi+lo)
#define AS_OFF    0
#define BS_OFF    (2*BUF_SZ)         // 40960
#define SMEM_SZ   (4*BUF_SZ)         // 81920

// ---------------- index computation ----------------
__global__ void idx_kernel(const float* __restrict__ grid, int* __restrict__ idx)
{
    int s = blockIdx.x * 256 + threadIdx.x;
    if (s >= NSAMP) return;
    int p  = s / 9;
    int t  = s - p * 9;
    int h  = p >> 8;
    int w  = p & 255;
    int kh = t / 3;
    int kw = t - kh * 3;
    const float* g = grid + ((size_t)(h * 3 + kh) * 768 + (w * 3 + kw)) * 2;
    float fx = rintf(((g[0] + 1.0f) * 0.5f) * 255.0f);
    float fy = rintf(((g[1] + 1.0f) * 0.5f) * 127.0f);
    int ix = (int)fminf(fmaxf(fx, 0.0f), 255.0f);
    int iy = (int)fminf(fmaxf(fy, 0.0f), 127.0f);
    idx[s] = iy * WW + ix;
}

// ---------------- transpose x[C][HW] -> XTh/XTl [HW][C] ----------------
__global__ void transpose_conv(const float* __restrict__ in,
                               __nv_bfloat16* __restrict__ oh, __nv_bfloat16* __restrict__ ol)
{
    __shared__ float tile[32][33];
    int c0 = blockIdx.x * 32;   // hw
    int r0 = blockIdx.y * 32;   // channel
    int tx = threadIdx.x, ty = threadIdx.y;
#pragma unroll
    for (int i = 0; i < 32; i += 8)
        tile[ty + i][tx] = in[(size_t)(r0 + ty + i) * HW + c0 + tx];
    __syncthreads();
#pragma unroll
    for (int i = 0; i < 32; i += 8) {
        float v = tile[tx][ty + i];
        __nv_bfloat16 h = __float2bfloat16(v);
        size_t o = (size_t)(c0 + ty + i) * CC + r0 + tx;
        oh[o] = h;
        ol[o] = __float2bfloat16(v - __bfloat162float(h));
    }
}

__global__ void conv_hilo(const float* __restrict__ src,
                          __nv_bfloat16* __restrict__ h, __nv_bfloat16* __restrict__ l)
{
    int i = blockIdx.x * 256 + threadIdx.x;
    float v = src[i];
    __nv_bfloat16 hi = __float2bfloat16(v);
    h[i] = hi;
    l[i] = __float2bfloat16(v - __bfloat162float(hi));
}

__global__ void concat_bias(const float* __restrict__ bq, const float* __restrict__ bk,
                            const float* __restrict__ bv, float* __restrict__ o)
{
    int i = blockIdx.x * 256 + threadIdx.x;   // 0..767
    o[i] = (i < 256) ? bq[i] : ((i < 512) ? bk[i - 256] : bv[i - 512]);
}

// ---------------- HMMA bf16-split GEMM ----------------
// C[M][N] = A[M][256] * B[N][256]^T + bias.  A,B bf16 hi/lo, K-contiguous rows.
// ROWBIAS: bias per m, else per n.
template<bool ROWBIAS>
__global__ __launch_bounds__(256, 1)
void hmma_gemm(const __nv_bfloat16* __restrict__ Ah, const __nv_bfloat16* __restrict__ Al,
               const __nv_bfloat16* __restrict__ Bh, const __nv_bfloat16* __restrict__ Bl,
               const float* __restrict__ bias, float* __restrict__ C, int ldc)
{
    extern __shared__ __align__(16) char sm[];
    uint32_t smb = smem_u32(sm);
    int tid = threadIdx.x;
    int m0 = blockIdx.y * 128, n0 = blockIdx.x * 128;

    // global load assignment: 2 threads per row, 2 uint4 chunks each per k-slice
    int grow_l = tid >> 1;            // 0..127
    int gcp    = (tid & 1) * 2;       // 0 or 2
    const uint4* gAh = (const uint4*)(Ah + (size_t)(m0 + grow_l) * 256) + gcp;
    const uint4* gAl = (const uint4*)(Al + (size_t)(m0 + grow_l) * 256) + gcp;
    const uint4* gBh = (const uint4*)(Bh + (size_t)(n0 + grow_l) * 256) + gcp;
    const uint4* gBl = (const uint4*)(Bl + (size_t)(n0 + grow_l) * 256) + gcp;

    uint4 rA[4], rB[4];
    int store_off = grow_l * LDS_ROW + gcp * 16;

    int wid = tid >> 5, lane = tid & 31;
    int wm = wid >> 2, wn = wid & 3;
    uint32_t aAddr[4], bAddr[2];
#pragma unroll
    for (int mt = 0; mt < 4; mt++)
        aAddr[mt] = smb + AS_OFF + (wm * 64 + mt * 16 + (lane & 15)) * LDS_ROW
                  + ((lane >> 4) * 16);
#pragma unroll
    for (int bt = 0; bt < 2; bt++)
        bAddr[bt] = smb + BS_OFF + (wn * 32 + bt * 16 + ((lane >> 4) & 1) * 8 + (lane & 7)) * LDS_ROW
                  + (((lane >> 3) & 1) * 16);

    float acc[4][4][4];
#pragma unroll
    for (int i = 0; i < 4; i++)
#pragma unroll
        for (int j = 0; j < 4; j++)
#pragma unroll
            for (int k = 0; k < 4; k++) acc[i][j][k] = 0.0f;

    // ---- prologue: load ks=0 ----
    rA[0] = gAh[0]; rA[1] = gAh[1]; rA[2] = gAl[0]; rA[3] = gAl[1];
    rB[0] = gBh[0]; rB[1] = gBh[1]; rB[2] = gBl[0]; rB[3] = gBl[1];
    {
        char* a = sm + AS_OFF + store_off;
        *(uint4*)a = rA[0]; *(uint4*)(a + 16) = rA[1];
        *(uint4*)(a + TILE_HB) = rA[2]; *(uint4*)(a + TILE_HB + 16) = rA[3];
        char* b = sm + BS_OFF + store_off;
        *(uint4*)b = rB[0]; *(uint4*)(b + 16) = rB[1];
        *(uint4*)(b + TILE_HB) = rB[2]; *(uint4*)(b + TILE_HB + 16) = rB[3];
    }
    __syncthreads();

#pragma unroll 1
    for (int ks = 0; ks < 8; ks++) {
        if (ks < 7) {
            int c = (ks + 1) * 4;
            rA[0] = gAh[c]; rA[1] = gAh[c + 1]; rA[2] = gAl[c]; rA[3] = gAl[c + 1];
            rB[0] = gBh[c]; rB[1] = gBh[c + 1]; rB[2] = gBl[c]; rB[3] = gBl[c + 1];
        }
        uint32_t boff = (ks & 1) * BUF_SZ;
#pragma unroll
        for (int kk = 0; kk < 2; kk++) {
            uint32_t ko = boff + kk * 32;
            uint32_t a_h[4][4], a_l[4][4];
#pragma unroll
            for (int mt = 0; mt < 4; mt++) {
                LDSM_X4(a_h[mt], aAddr[mt] + ko);
                LDSM_X4(a_l[mt], aAddr[mt] + ko + TILE_HB);
            }
            uint32_t b_h[2][4], b_l[2][4];
#pragma unroll
            for (int bt = 0; bt < 2; bt++) {
                LDSM_X4(b_h[bt], bAddr[bt] + ko);
                LDSM_X4(b_l[bt], bAddr[bt] + ko + TILE_HB);
            }
#pragma unroll
            for (int mt = 0; mt < 4; mt++)
#pragma unroll
                for (int nt = 0; nt < 4; nt++) {
                    uint32_t* bh = &b_h[nt >> 1][(nt & 1) * 2];
                    uint32_t* bl = &b_l[nt >> 1][(nt & 1) * 2];
                    MMA16816(acc[mt][nt], a_h[mt], bh);
                    MMA16816(acc[mt][nt], a_h[mt], bl);
                    MMA16816(acc[mt][nt], a_l[mt], bh);
                }
        }
        if (ks < 7) {
            uint32_t nb = ((ks + 1) & 1) * BUF_SZ;
            char* a = sm + AS_OFF + nb + store_off;
            *(uint4*)a = rA[0]; *(uint4*)(a + 16) = rA[1];
            *(uint4*)(a + TILE_HB) = rA[2]; *(uint4*)(a + TILE_HB + 16) = rA[3];
            char* b = sm + BS_OFF + nb + store_off;
            *(uint4*)b = rB[0]; *(uint4*)(b + 16) = rB[1];
            *(uint4*)(b + TILE_HB) = rB[2]; *(uint4*)(b + TILE_HB + 16) = rB[3];
            __syncthreads();
        }
    }

    // ---- epilogue ----
#pragma unroll
    for (int mt = 0; mt < 4; mt++) {
        int r0 = m0 + wm * 64 + mt * 16 + (lane >> 2);
        float rb0 = 0.f, rb1 = 0.f;
        if (ROWBIAS) { rb0 = bias[r0]; rb1 = bias[r0 + 8]; }
#pragma unroll
        for (int nt = 0; nt < 4; nt++) {
            int col = n0 + wn * 32 + nt * 8 + (lane & 3) * 2;
            float cb0 = 0.f, cb1 = 0.f;
            if (!ROWBIAS) { cb0 = bias[col]; cb1 = bias[col + 1]; }
            float* p = C + (size_t)r0 * ldc + col;
            float2 v;
            v.x = acc[mt][nt][0] + (ROWBIAS ? rb0 : cb0);
            v.y = acc[mt][nt][1] + (ROWBIAS ? rb0 : cb1);
            *(float2*)p = v;
            v.x = acc[mt][nt][2] + (ROWBIAS ? rb1 : cb0);
            v.y = acc[mt][nt][3] + (ROWBIAS ? rb1 : cb1);
            *(float2*)(p + (size_t)8 * ldc) = v;
        }
    }
}

// ---------------- attention: gather projected K/V rows, 9-tap softmax ----------------
// QKV [pixel][768] = Q|K|V.  OUT bf16 hi/lo pixel-major [p][256].
__global__ __launch_bounds__(256)
void attn_kernel(const float* __restrict__ QKV, const int* __restrict__ idx,
                 __nv_bfloat16* __restrict__ OUTh, __nv_bfloat16* __restrict__ OUTl)
{
    int p0   = blockIdx.x << 5;
    int warp = threadIdx.x >> 5;
    int lane = threadIdx.x & 31;
    const float scale = 0.17677669529663687f;  // 1/sqrt(32)

#pragma unroll 1
    for (int task = warp; task < 256; task += 8) {
        int p  = task >> 3;
        int h  = task & 7;
        int pg = p0 + p;
        const int* ip = idx + pg * 9;
        int r[9];
#pragma unroll
        for (int t = 0; t < 9; t++) r[t] = ip[t];
        int cb = h * 32 + lane;
        float qd = QKV[(size_t)pg * 768 + cb];
        float kv[9], vv[9];
#pragma unroll
        for (int t = 0; t < 9; t++) kv[t] = QKV[(size_t)r[t] * 768 + 256 + cb];
#pragma unroll
        for (int t = 0; t < 9; t++) vv[t] = QKV[(size_t)r[t] * 768 + 512 + cb];
        float lg[9];
#pragma unroll
        for (int t = 0; t < 9; t++) {
            float prod = qd * kv[t];
#pragma unroll
            for (int off = 16; off > 0; off >>= 1)
                prod += __shfl_xor_sync(0xffffffffu, prod, off);
            lg[t] = prod * scale;
        }
        float mx = lg[0];
#pragma unroll
        for (int t = 1; t < 9; t++) mx = fmaxf(mx, lg[t]);
        float den = 0.0f, e[9];
#pragma unroll
        for (int t = 0; t < 9; t++) { e[t] = __expf(lg[t] - mx); den += e[t]; }
        float inv = 1.0f / den;
        float o = 0.0f;
#pragma unroll
        for (int t = 0; t < 9; t++) o += e[t] * vv[t];
        float val = o * inv;
        __nv_bfloat16 hi = __float2bfloat16(val);
        size_t oi = (size_t)pg * 256 + cb;
        OUTh[oi] = hi;
        OUTl[oi] = __float2bfloat16(val - __bfloat162float(hi));
    }
}

// ---------------- launch ----------------
extern "C" void kernel_launch(void* const* d_in, const int* in_sizes, int n_in,
                              void* d_out, int out_size)
{
    const float* x   = (const float*)d_in[0];
    const float* grd = (const float*)d_in[1];
    const float* wq  = (const float*)d_in[2];
    const float* bq  = (const float*)d_in[3];
    const float* wk  = (const float*)d_in[4];
    const float* bk  = (const float*)d_in[5];
    const float* wv  = (const float*)d_in[6];
    const float* bv  = (const float*)d_in[7];
    const float* wo  = (const float*)d_in[8];
    const float* bo  = (const float*)d_in[9];
    float* y = (float*)d_out;

    __nv_bfloat16 *XTh, *XTl, *Wh, *Wl, *OUTh, *OUTl;
    float *QKV, *bqkv;
    int* idx;
    cudaGetSymbolAddress((void**)&XTh,  g_XTh);
    cudaGetSymbolAddress((void**)&XTl,  g_XTl);
    cudaGetSymbolAddress((void**)&idx,  g_idx);
    cudaGetSymbolAddress((void**)&Wh,   g_Wh);
    cudaGetSymbolAddress((void**)&Wl,   g_Wl);
    cudaGetSymbolAddress((void**)&QKV,  g_QKV);
    cudaGetSymbolAddress((void**)&bqkv, g_bqkv);
    cudaGetSymbolAddress((void**)&OUTh, g_OUTh);
    cudaGetSymbolAddress((void**)&OUTl, g_OUTl);

    cudaFuncSetAttribute(hmma_gemm<false>, cudaFuncAttributeMaxDynamicSharedMemorySize, SMEM_SZ);
    cudaFuncSetAttribute(hmma_gemm<true >, cudaFuncAttributeMaxDynamicSharedMemorySize, SMEM_SZ);

    // 1) gather indices
    idx_kernel<<<NSAMP / 256, 256>>>(grd, idx);

    // 2) x -> XT bf16 hi/lo ; weights -> bf16 hi/lo ; bias concat
    transpose_conv<<<dim3(HW / 32, CC / 32), dim3(32, 8)>>>(x, XTh, XTl);
    conv_hilo<<<CC * CC / 256, 256>>>(wq, Wh + 0 * CC * CC, Wl + 0 * CC * CC);
    conv_hilo<<<CC * CC / 256, 256>>>(wk, Wh + 1 * CC * CC, Wl + 1 * CC * CC);
    conv_hilo<<<CC * CC / 256, 256>>>(wv, Wh + 2 * CC * CC, Wl + 2 * CC * CC);
    conv_hilo<<<CC * CC / 256, 256>>>(wo, Wh + 3 * CC * CC, Wl + 3 * CC * CC);
    concat_bias<<<3, 256>>>(bq, bk, bv, bqkv);

    // 3) fused QKV projection over DISTINCT pixels only (project-then-gather):
    //    QKV[p][n] = XT[p][c] * Wqkv[n][c]^T + b[n],  n in [0,768)
    hmma_gemm<false><<<dim3(6, HW / 128), 256, SMEM_SZ>>>(
        XTh, XTl, Wh, Wl, bqkv, QKV, 768);

    // 4) attention with gathered projected rows -> OUT bf16 hi/lo [p][c]
    attn_kernel<<<HW / 32, 256>>>(QKV, idx, OUTh, OUTl);

    // 5) y[o][p] = wo[o][c] * OUT[p][c]^T + bo[o]
    hmma_gemm<true><<<dim3(HW / 128, CC / 128), 256, SMEM_SZ>>>(
        Wh + 3 * CC * CC, Wl + 3 * CC * CC, OUTh, OUTl, bo, y, HW);
}